// round 3
// baseline (speedup 1.0000x reference)
#include <cuda_runtime.h>

#define BS 8
#define LQ 2049
#define NC 32
#define NH 16
#define KS 5
#define NL 4
#define NPOS (BS*LQ)            // 16392
#define NTILE 513               // ceil(NPOS/32)
#define KA 584                  // 512 Gsum + 32 fsum + 32 enc + 1 one + 7 pad
#define TILE_ELEMS (KA*NC)      // 18688
#define ASTRIDE 596             // padded A row stride (conflict-free LDS.128)
#define SMEM_FLOATS (32*ASTRIDE + 2048)
#define SMEM_BYTES (SMEM_FLOATS*4)             // 84480 B

// -------- device scratch --------
__device__ __align__(16) float g_times[BS*LQ];
__device__ __align__(16) float g_enc[NPOS*NC];          // activated features (input of layer)
__device__ __align__(16) float g_raw[NTILE*32*NC];      // pre-BN output of layer
__device__ __align__(16) float g_H2[NL*NPOS*KS*NH];     // 21 MB, all layers upfront
__device__ __align__(16) float g_Wc[NL*TILE_ELEMS];
__device__ __align__(16) float g_psum[NTILE*NC];
__device__ __align__(16) float g_psq[NTILE*NC];
__device__ __align__(16) float g_bn[2*NC];
__device__ int g_maxtype;

__device__ __forceinline__ float lrelu(float x) { return x >= 0.f ? x : 0.1f*x; }

// -------- prep: global max of event_types --------
__global__ void k_max(const int* __restrict__ types) {
    __shared__ int sm[1024];
    int t = threadIdx.x, m = 0;
    for (int i = t; i < BS*2048; i += 1024) m = max(m, types[i]);
    sm[t] = m;
    for (int s = 512; s > 0; s >>= 1) {
        __syncthreads();
        if (t < s) sm[t] = max(sm[t], sm[t+s]);
    }
    __syncthreads();
    if (t == 0) g_maxtype = sm[0];
}

// -------- prep: build times + embedded enc --------
__global__ void k_build(const float* __restrict__ et, const int* __restrict__ ty,
                        const float* __restrict__ emb) {
    int idx = blockIdx.x*blockDim.x + threadIdx.x;
    if (idx >= NPOS*NC) return;
    int pos = idx >> 5, c = idx & 31;
    int b = pos / LQ, l = pos - b*LQ;
    float tv = (l == 0) ? 0.f : et[b*2048 + l - 1];
    if (c == 0) g_times[pos] = tv;
    int tp = (l == 0) ? (g_maxtype + 1) : ty[b*2048 + l - 1];
    g_enc[idx] = (tp == 0) ? 0.f : emb[tp*NC + c];
}

// -------- prep: combined weight matrix Wc[layer][584][32] --------
__global__ void k_wc(const float* __restrict__ k3W, const float* __restrict__ k3b,
                     const float* __restrict__ skipW, const float* __restrict__ skipb) {
    int idx = blockIdx.x*blockDim.x + threadIdx.x;
    if (idx >= NL*TILE_ELEMS) return;
    int layer = idx / TILE_ELEMS;
    int rem = idx - layer*TILE_ELEMS;
    int r = rem >> 5, d = rem & 31;
    float v;
    if (r < 512)      v = k3W[layer*16384 + r*32 + d];
    else if (r < 544) v = k3b[layer*1024 + (r-512)*32 + d];
    else if (r < 576) v = skipW[layer*1024 + (r-544)*32 + d];
    else if (r == 576) v = skipb[layer*32 + d];
    else v = 0.f;
    g_Wc[idx] = v;
}

// -------- ALL layers' kernel MLPs upfront: H2[layer][pos][k][16] --------
__global__ __launch_bounds__(256) void k_mlp_all(
        const float* __restrict__ k1W, const float* __restrict__ k1b,
        const float* __restrict__ k2W, const float* __restrict__ k2b) {
    int layer = blockIdx.y;
    int dil = 1 << layer;
    __shared__ float sk1[NH], sk1b[NH], sk2[NH*NH], sk2b[NH];
    int t = threadIdx.x;
    if (t < NH) { sk1[t] = k1W[layer*NH + t]; sk1b[t] = k1b[layer*NH + t];
                  sk2b[t] = k2b[layer*NH + t]; }
    sk2[t] = k2W[layer*NH*NH + t];
    __syncthreads();
    int idx = blockIdx.x*256 + t;
    if (idx >= NPOS*KS) return;
    int pos = idx / KS, k = idx - pos*KS;
    int b = pos / LQ, l = pos - b*LQ;
    float out[NH];
    bool valid = false;
    int j = l - k*dil;
    float tl = g_times[pos];
    if (j >= 0 && tl != 0.f) {
        float tj = g_times[b*LQ + j];
        if (tj != 0.f) {
            valid = true;
            float dt = tl - tj;
            float h1[NH];
            #pragma unroll
            for (int h = 0; h < NH; h++) h1[h] = lrelu(fmaf(dt, sk1[h], sk1b[h]));
            #pragma unroll
            for (int hh = 0; hh < NH; hh++) {
                float s = sk2b[hh];
                #pragma unroll
                for (int x = 0; x < NH; x++) s = fmaf(h1[x], sk2[x*NH + hh], s);
                out[hh] = lrelu(s);
            }
        }
    }
    if (!valid) {
        #pragma unroll
        for (int h = 0; h < NH; h++) out[h] = 0.f;
    }
    float* dst = g_H2 + (size_t)((layer*NPOS + pos)*KS + k)*NH;
    #pragma unroll
    for (int q = 0; q < 4; q++)
        *reinterpret_cast<float4*>(dst + 4*q) =
            make_float4(out[4*q], out[4*q+1], out[4*q+2], out[4*q+3]);
}

// -------- fused: gather/Gsum build (smem A) + GEMM + BN partials --------
__global__ __launch_bounds__(256) void k_fused(int layer, int dil) {
    extern __shared__ float sm[];
    float* s_A   = sm;                // 32*ASTRIDE
    float* s_ps  = s_A + 32*ASTRIDE;  // 1024
    float* s_ps2 = s_ps + 1024;       // 1024
    int t = threadIdx.x;
    int lane = t & 31, warp = t >> 5;
    int tile = blockIdx.x;

    // ---- phase A: 8 warps x 4 positions; lane = channel c ----
    #pragma unroll
    for (int wp = 0; wp < 4; wp++) {
        int p = warp*4 + wp;
        int pos = tile*32 + p;
        int cpos = pos < NPOS ? pos : NPOS-1;
        float one = pos < NPOS ? 1.f : 0.f;
        int b = cpos / LQ, l = cpos - b*LQ;
        float tl = g_times[cpos];
        float en = g_enc[cpos*NC + lane] * one;

        // batched, unconditional loads for all 5 taps
        float gv[KS];
        #pragma unroll
        for (int k = 0; k < KS; k++) {
            int j = l - k*dil;
            int pj = j >= 0 ? cpos - k*dil : cpos;
            float tj = g_times[pj];
            bool ok = (j >= 0) && (tj != 0.f) && (tl != 0.f) && (pos < NPOS);
            float g = g_enc[pj*NC + lane];
            gv[k] = ok ? g : 0.f;
        }
        float fs = 0.f;
        float G[NH];
        #pragma unroll
        for (int h = 0; h < NH; h++) G[h] = 0.f;
        const float* h2p = g_H2 + (size_t)((layer*NPOS + cpos)*KS)*NH;
        #pragma unroll
        for (int k = 0; k < KS; k++) {
            float g = gv[k];
            fs += g;
            float4 h0 = *reinterpret_cast<const float4*>(h2p + k*NH + 0);
            float4 h1 = *reinterpret_cast<const float4*>(h2p + k*NH + 4);
            float4 h2 = *reinterpret_cast<const float4*>(h2p + k*NH + 8);
            float4 h3 = *reinterpret_cast<const float4*>(h2p + k*NH + 12);
            G[0] = fmaf(h0.x, g, G[0]);  G[1] = fmaf(h0.y, g, G[1]);
            G[2] = fmaf(h0.z, g, G[2]);  G[3] = fmaf(h0.w, g, G[3]);
            G[4] = fmaf(h1.x, g, G[4]);  G[5] = fmaf(h1.y, g, G[5]);
            G[6] = fmaf(h1.z, g, G[6]);  G[7] = fmaf(h1.w, g, G[7]);
            G[8] = fmaf(h2.x, g, G[8]);  G[9] = fmaf(h2.y, g, G[9]);
            G[10] = fmaf(h2.z, g, G[10]); G[11] = fmaf(h2.w, g, G[11]);
            G[12] = fmaf(h3.x, g, G[12]); G[13] = fmaf(h3.y, g, G[13]);
            G[14] = fmaf(h3.z, g, G[14]); G[15] = fmaf(h3.w, g, G[15]);
        }
        float* row = s_A + p*ASTRIDE;
        #pragma unroll
        for (int h = 0; h < NH; h++) row[h*32 + lane] = G[h];
        row[512 + lane] = fs;
        row[544 + lane] = en;
        if (lane == 0) row[576] = one;
        if (lane < 7)  row[577 + lane] = 0.f;
    }
    __syncthreads();

    // ---- GEMM: 256 threads, each 1 pos x 4 d; K=584 in float4 chunks ----
    int tx = t & 7;        // d0 = 4*tx
    int ty = t >> 3;       // pos within tile
    const float* Ap = s_A + ty*ASTRIDE;
    const float* Wl = g_Wc + layer*TILE_ELEMS + 4*tx;
    float ax = 0.f, ay = 0.f, az = 0.f, aw = 0.f;
    #pragma unroll 2
    for (int kk = 0; kk < KA/4; kk++) {
        float4 a  = *reinterpret_cast<const float4*>(Ap + kk*4);
        float4 w0 = *reinterpret_cast<const float4*>(Wl + (4*kk+0)*32);
        float4 w1 = *reinterpret_cast<const float4*>(Wl + (4*kk+1)*32);
        float4 w2 = *reinterpret_cast<const float4*>(Wl + (4*kk+2)*32);
        float4 w3 = *reinterpret_cast<const float4*>(Wl + (4*kk+3)*32);
        ax = fmaf(a.x, w0.x, ax); ay = fmaf(a.x, w0.y, ay);
        az = fmaf(a.x, w0.z, az); aw = fmaf(a.x, w0.w, aw);
        ax = fmaf(a.y, w1.x, ax); ay = fmaf(a.y, w1.y, ay);
        az = fmaf(a.y, w1.z, az); aw = fmaf(a.y, w1.w, aw);
        ax = fmaf(a.z, w2.x, ax); ay = fmaf(a.z, w2.y, ay);
        az = fmaf(a.z, w2.z, az); aw = fmaf(a.z, w2.w, aw);
        ax = fmaf(a.w, w3.x, ax); ay = fmaf(a.w, w3.y, ay);
        az = fmaf(a.w, w3.z, az); aw = fmaf(a.w, w3.w, aw);
    }
    *reinterpret_cast<float4*>(g_raw + (size_t)(tile*32 + ty)*NC + 4*tx) =
        make_float4(ax, ay, az, aw);

    // ---- BN partials (deterministic) ----
    s_ps [ty*32 + 4*tx+0] = ax;  s_ps2[ty*32 + 4*tx+0] = ax*ax;
    s_ps [ty*32 + 4*tx+1] = ay;  s_ps2[ty*32 + 4*tx+1] = ay*ay;
    s_ps [ty*32 + 4*tx+2] = az;  s_ps2[ty*32 + 4*tx+2] = az*az;
    s_ps [ty*32 + 4*tx+3] = aw;  s_ps2[ty*32 + 4*tx+3] = aw*aw;
    __syncthreads();
    if (t < 32) {
        float s = 0.f, s2 = 0.f;
        #pragma unroll
        for (int r = 0; r < 32; r++) { s += s_ps[r*32 + t]; s2 += s_ps2[r*32 + t]; }
        g_psum[tile*32 + t] = s;
        g_psq [tile*32 + t] = s2;
    }
}

// -------- BN stats: 1024 threads, 32-way parallel per channel --------
__global__ __launch_bounds__(1024) void k_stats(int layer, const float* __restrict__ gamma,
                        const float* __restrict__ beta) {
    __shared__ float ss[32][33], ss2[32][33];
    int t = threadIdx.x;      // 1024
    int r = t >> 5, n = t & 31;
    float s = 0.f, s2 = 0.f;
    #pragma unroll 4
    for (int b = r; b < NTILE; b += 32) {
        s += g_psum[b*32 + n];
        s2 += g_psq[b*32 + n];
    }
    ss[r][n] = s; ss2[r][n] = s2;
    __syncthreads();
    if (t < 32) {
        float fs = 0.f, fs2 = 0.f;
        #pragma unroll
        for (int i = 0; i < 32; i++) { fs += ss[i][t]; fs2 += ss2[i][t]; }
        float inv = 1.0f / (float)NPOS;
        float mu = fs * inv;
        float var = fs2 * inv - mu*mu;
        float scale = rsqrtf(var + 1e-5f) * gamma[layer*32 + t];
        g_bn[t]      = scale;
        g_bn[32 + t] = beta[layer*32 + t] - mu*scale;
    }
}

// -------- activate: BN + leaky ReLU -> next layer's features (or output) --------
__global__ void k_act(float* dst) {
    int idx = blockIdx.x*blockDim.x + threadIdx.x;
    if (idx >= NPOS*NC) return;
    int n = idx & 31;
    float v = fmaf(g_raw[idx], g_bn[n], g_bn[32 + n]);
    v = v >= 0.f ? v : 0.1f*v;
    float* o = dst ? dst : g_enc;
    o[idx] = v;
}

extern "C" void kernel_launch(void* const* d_in, const int* in_sizes, int n_in,
                              void* d_out, int out_size) {
    const float* event_times = (const float*)d_in[0];
    const int*   event_types = (const int*)  d_in[1];
    const float* emb   = (const float*)d_in[2];
    const float* k1W   = (const float*)d_in[3];
    const float* k1b   = (const float*)d_in[4];
    const float* k2W   = (const float*)d_in[5];
    const float* k2b   = (const float*)d_in[6];
    const float* k3W   = (const float*)d_in[7];
    const float* k3b   = (const float*)d_in[8];
    const float* skipW = (const float*)d_in[9];
    const float* skipb = (const float*)d_in[10];
    const float* gamma = (const float*)d_in[11];
    const float* beta  = (const float*)d_in[12];
    float* out = (float*)d_out;

    static int attr_done = 0;
    if (!attr_done) {
        cudaFuncSetAttribute(k_fused, cudaFuncAttributeMaxDynamicSharedMemorySize,
                             SMEM_BYTES);
        attr_done = 1;
    }

    k_max<<<1, 1024>>>(event_types);
    k_build<<<(NPOS*NC + 255)/256, 256>>>(event_times, event_types, emb);
    k_wc<<<(NL*TILE_ELEMS + 255)/256, 256>>>(k3W, k3b, skipW, skipb);
    {
        dim3 g((NPOS*KS + 255)/256, NL);
        k_mlp_all<<<g, 256>>>(k1W, k1b, k2W, k2b);
    }

    const int dil[NL] = {1, 2, 4, 8};
    for (int i = 0; i < NL; i++) {
        k_fused<<<NTILE, 256, SMEM_BYTES>>>(i, dil[i]);
        k_stats<<<1, 1024>>>(i, gamma, beta);
        k_act<<<(NPOS*NC + 255)/256, 256>>>(i == NL-1 ? out : nullptr);
    }
}

// round 6
// speedup vs baseline: 1.7831x; 1.7831x over previous
#include <cuda_runtime.h>

#define BS 8
#define LQ 2049
#define NC 32
#define NH 16
#define KS 5
#define NL 4
#define NPOS (BS*LQ)            // 16392
#define TILE 16
#define NTILE 1025              // ceil(NPOS/16)
#define KA 584                  // 512 Gsum + 32 fsum + 32 enc + 1 one + 7 pad
#define TILE_ELEMS (KA*NC)      // 18688
#define ASTRIDE 596             // padded A row stride

// -------- device scratch --------
__device__ __align__(16) float g_times[BS*LQ];
__device__ __align__(16) float g_enc[NPOS*NC];
__device__ __align__(16) float g_raw[2][NTILE*TILE*NC];   // ping-pong
__device__ __align__(16) float g_H2[NL*NPOS*KS*NH];       // 21 MB, all layers
__device__ __align__(16) float g_Wc[NL*TILE_ELEMS];
__device__ __align__(16) float g_psum[NTILE*NC];
__device__ __align__(16) float g_psq[NTILE*NC];
__device__ __align__(16) float g_bn[2*NC];
__device__ int g_maxtype;

__device__ __forceinline__ float lrelu(float x) { return x >= 0.f ? x : 0.1f*x; }

// -------- prep: global max of event_types --------
__global__ void k_max(const int* __restrict__ types) {
    __shared__ int sm[1024];
    int t = threadIdx.x, m = 0;
    for (int i = t; i < BS*2048; i += 1024) m = max(m, types[i]);
    sm[t] = m;
    for (int s = 512; s > 0; s >>= 1) {
        __syncthreads();
        if (t < s) sm[t] = max(sm[t], sm[t+s]);
    }
    __syncthreads();
    if (t == 0) g_maxtype = sm[0];
}

// -------- prep: build times + embedded enc --------
__global__ void k_build(const float* __restrict__ et, const int* __restrict__ ty,
                        const float* __restrict__ emb) {
    int idx = blockIdx.x*blockDim.x + threadIdx.x;
    if (idx >= NPOS*NC) return;
    int pos = idx >> 5, c = idx & 31;
    int b = pos / LQ, l = pos - b*LQ;
    float tv = (l == 0) ? 0.f : et[b*2048 + l - 1];
    if (c == 0) g_times[pos] = tv;
    int tp = (l == 0) ? (g_maxtype + 1) : ty[b*2048 + l - 1];
    g_enc[idx] = (tp == 0) ? 0.f : emb[tp*NC + c];
}

// -------- prep: combined weight matrix Wc[layer][584][32] --------
__global__ void k_wc(const float* __restrict__ k3W, const float* __restrict__ k3b,
                     const float* __restrict__ skipW, const float* __restrict__ skipb) {
    int idx = blockIdx.x*blockDim.x + threadIdx.x;
    if (idx >= NL*TILE_ELEMS) return;
    int layer = idx / TILE_ELEMS;
    int rem = idx - layer*TILE_ELEMS;
    int r = rem >> 5, d = rem & 31;
    float v;
    if (r < 512)      v = k3W[layer*16384 + r*32 + d];
    else if (r < 544) v = k3b[layer*1024 + (r-512)*32 + d];
    else if (r < 576) v = skipW[layer*1024 + (r-544)*32 + d];
    else if (r == 576) v = skipb[layer*32 + d];
    else v = 0.f;
    g_Wc[idx] = v;
}

// -------- ALL layers' kernel MLPs upfront: H2[layer][pos][k][16] --------
__global__ __launch_bounds__(256) void k_mlp_all(
        const float* __restrict__ k1W, const float* __restrict__ k1b,
        const float* __restrict__ k2W, const float* __restrict__ k2b) {
    int layer = blockIdx.y;
    int dil = 1 << layer;
    __shared__ float sk1[NH], sk1b[NH], sk2[NH*NH], sk2b[NH];
    int t = threadIdx.x;
    if (t < NH) { sk1[t] = k1W[layer*NH + t]; sk1b[t] = k1b[layer*NH + t];
                  sk2b[t] = k2b[layer*NH + t]; }
    sk2[t] = k2W[layer*NH*NH + t];
    __syncthreads();
    int idx = blockIdx.x*256 + t;
    if (idx >= NPOS*KS) return;
    int pos = idx / KS, k = idx - pos*KS;
    int b = pos / LQ, l = pos - b*LQ;
    float out[NH];
    bool valid = false;
    int j = l - k*dil;
    float tl = g_times[pos];
    if (j >= 0 && tl != 0.f) {
        float tj = g_times[b*LQ + j];
        if (tj != 0.f) {
            valid = true;
            float dt = tl - tj;
            float h1[NH];
            #pragma unroll
            for (int h = 0; h < NH; h++) h1[h] = lrelu(fmaf(dt, sk1[h], sk1b[h]));
            #pragma unroll
            for (int hh = 0; hh < NH; hh++) {
                float s = sk2b[hh];
                #pragma unroll
                for (int x = 0; x < NH; x++) s = fmaf(h1[x], sk2[x*NH + hh], s);
                out[hh] = lrelu(s);
            }
        }
    }
    if (!valid) {
        #pragma unroll
        for (int h = 0; h < NH; h++) out[h] = 0.f;
    }
    float* dst = g_H2 + (size_t)((layer*NPOS + pos)*KS + k)*NH;
    #pragma unroll
    for (int q = 0; q < 4; q++)
        *reinterpret_cast<float4*>(dst + 4*q) =
            make_float4(out[4*q], out[4*q+1], out[4*q+2], out[4*q+3]);
}

// -------- fused: gather/Gsum build (static smem A) + GEMM + BN partials ----
__global__ __launch_bounds__(256) void k_fused(int layer, int dil, int first) {
    __shared__ float s_bn[64];
    __shared__ float s_A[TILE*ASTRIDE];     // 16*596*4 = 38144 B
    __shared__ float s_ps[TILE*NC], s_ps2[TILE*NC];
    int t = threadIdx.x;
    int lane = t & 31, warp = t >> 5;
    int tile = blockIdx.x;
    const float* raw_in = g_raw[(layer + 1) & 1];
    float* raw_out = g_raw[layer & 1];

    if (!first && t < 64) s_bn[t] = g_bn[t];
    __syncthreads();

    // ---- phase A: 8 warps x 2 positions; lane = channel c ----
    #pragma unroll
    for (int wp = 0; wp < 2; wp++) {
        int p = warp*2 + wp;
        int pos = tile*TILE + p;
        float G[NH];
        #pragma unroll
        for (int h = 0; h < NH; h++) G[h] = 0.f;
        float fs = 0.f, en = 0.f, one = 0.f;
        if (pos < NPOS) {
            one = 1.f;
            int b = pos / LQ, l = pos - b*LQ;
            float tl = g_times[pos];
            if (first) en = g_enc[pos*NC + lane];
            else {
                float v = fmaf(raw_in[pos*NC + lane], s_bn[lane], s_bn[32 + lane]);
                en = v >= 0.f ? v : 0.1f*v;
            }
            if (tl != 0.f) {
                const float* h2p = g_H2 + (size_t)((layer*NPOS + pos)*KS)*NH;
                for (int k = 0; k < KS; k++) {
                    int j = l - k*dil;
                    if (j < 0) break;
                    float tj = g_times[b*LQ + j];
                    if (tj != 0.f) {
                        int pj = pos - k*dil;
                        float g;
                        if (first) g = g_enc[pj*NC + lane];
                        else {
                            float v = fmaf(raw_in[pj*NC + lane], s_bn[lane], s_bn[32 + lane]);
                            g = v >= 0.f ? v : 0.1f*v;
                        }
                        fs += g;
                        float4 h0 = *reinterpret_cast<const float4*>(h2p + k*NH + 0);
                        float4 h1 = *reinterpret_cast<const float4*>(h2p + k*NH + 4);
                        float4 h2 = *reinterpret_cast<const float4*>(h2p + k*NH + 8);
                        float4 h3 = *reinterpret_cast<const float4*>(h2p + k*NH + 12);
                        G[0] = fmaf(h0.x, g, G[0]);  G[1] = fmaf(h0.y, g, G[1]);
                        G[2] = fmaf(h0.z, g, G[2]);  G[3] = fmaf(h0.w, g, G[3]);
                        G[4] = fmaf(h1.x, g, G[4]);  G[5] = fmaf(h1.y, g, G[5]);
                        G[6] = fmaf(h1.z, g, G[6]);  G[7] = fmaf(h1.w, g, G[7]);
                        G[8] = fmaf(h2.x, g, G[8]);  G[9] = fmaf(h2.y, g, G[9]);
                        G[10] = fmaf(h2.z, g, G[10]); G[11] = fmaf(h2.w, g, G[11]);
                        G[12] = fmaf(h3.x, g, G[12]); G[13] = fmaf(h3.y, g, G[13]);
                        G[14] = fmaf(h3.z, g, G[14]); G[15] = fmaf(h3.w, g, G[15]);
                    }
                }
            }
        }
        float* row = s_A + p*ASTRIDE;
        #pragma unroll
        for (int h = 0; h < NH; h++) row[h*32 + lane] = G[h];
        row[512 + lane] = fs;
        row[544 + lane] = en;
        if (lane == 0) row[576] = one;
        if (lane < 7)  row[577 + lane] = 0.f;
    }
    __syncthreads();

    // ---- GEMM: 256 threads, each 1 pos x 2 d; K=584 in float4 chunks ----
    int tx = t & 15;       // d0 = 2*tx
    int ty = t >> 4;       // pos within tile (0..15)
    const float* Ap = s_A + ty*ASTRIDE;
    const float* Wl = g_Wc + layer*TILE_ELEMS + 2*tx;
    float ax = 0.f, ay = 0.f;
    #pragma unroll 4
    for (int kk = 0; kk < KA/4; kk++) {
        float4 a  = *reinterpret_cast<const float4*>(Ap + kk*4);
        float2 w0 = *reinterpret_cast<const float2*>(Wl + (4*kk+0)*32);
        float2 w1 = *reinterpret_cast<const float2*>(Wl + (4*kk+1)*32);
        float2 w2 = *reinterpret_cast<const float2*>(Wl + (4*kk+2)*32);
        float2 w3 = *reinterpret_cast<const float2*>(Wl + (4*kk+3)*32);
        ax = fmaf(a.x, w0.x, ax); ay = fmaf(a.x, w0.y, ay);
        ax = fmaf(a.y, w1.x, ax); ay = fmaf(a.y, w1.y, ay);
        ax = fmaf(a.z, w2.x, ax); ay = fmaf(a.z, w2.y, ay);
        ax = fmaf(a.w, w3.x, ax); ay = fmaf(a.w, w3.y, ay);
    }
    *reinterpret_cast<float2*>(raw_out + (size_t)(tile*TILE + ty)*NC + 2*tx) =
        make_float2(ax, ay);

    // ---- BN partials (deterministic) ----
    s_ps [ty*32 + 2*tx+0] = ax;  s_ps2[ty*32 + 2*tx+0] = ax*ax;
    s_ps [ty*32 + 2*tx+1] = ay;  s_ps2[ty*32 + 2*tx+1] = ay*ay;
    __syncthreads();
    if (t < 32) {
        float s = 0.f, s2 = 0.f;
        #pragma unroll
        for (int r = 0; r < TILE; r++) { s += s_ps[r*32 + t]; s2 += s_ps2[r*32 + t]; }
        g_psum[tile*32 + t] = s;
        g_psq [tile*32 + t] = s2;
    }
}

// -------- BN stats: 1024 threads, 32-way parallel per channel --------
__global__ __launch_bounds__(1024) void k_stats(int layer, const float* __restrict__ gamma,
                        const float* __restrict__ beta) {
    __shared__ float ss[32][33], ss2[32][33];
    int t = threadIdx.x;      // 1024
    int r = t >> 5, n = t & 31;
    float s = 0.f, s2 = 0.f;
    #pragma unroll 4
    for (int b = r; b < NTILE; b += 32) {
        s += g_psum[b*32 + n];
        s2 += g_psq[b*32 + n];
    }
    ss[r][n] = s; ss2[r][n] = s2;
    __syncthreads();
    if (t < 32) {
        float fs = 0.f, fs2 = 0.f;
        #pragma unroll
        for (int i = 0; i < 32; i++) { fs += ss[i][t]; fs2 += ss2[i][t]; }
        float inv = 1.0f / (float)NPOS;
        float mu = fs * inv;
        float var = fs2 * inv - mu*mu;
        float scale = rsqrtf(var + 1e-5f) * gamma[layer*32 + t];
        g_bn[t]      = scale;
        g_bn[32 + t] = beta[layer*32 + t] - mu*scale;
    }
}

// -------- final apply: BN + leaky ReLU -> output --------
__global__ void k_apply(float* dst, int buf) {
    int idx = blockIdx.x*blockDim.x + threadIdx.x;
    if (idx >= NPOS*NC) return;
    int n = idx & 31;
    float v = fmaf(g_raw[buf][idx], g_bn[n], g_bn[32 + n]);
    dst[idx] = v >= 0.f ? v : 0.1f*v;
}

extern "C" void kernel_launch(void* const* d_in, const int* in_sizes, int n_in,
                              void* d_out, int out_size) {
    const float* event_times = (const float*)d_in[0];
    const int*   event_types = (const int*)  d_in[1];
    const float* emb   = (const float*)d_in[2];
    const float* k1W   = (const float*)d_in[3];
    const float* k1b   = (const float*)d_in[4];
    const float* k2W   = (const float*)d_in[5];
    const float* k2b   = (const float*)d_in[6];
    const float* k3W   = (const float*)d_in[7];
    const float* k3b   = (const float*)d_in[8];
    const float* skipW = (const float*)d_in[9];
    const float* skipb = (const float*)d_in[10];
    const float* gamma = (const float*)d_in[11];
    const float* beta  = (const float*)d_in[12];
    float* out = (float*)d_out;

    k_max<<<1, 1024>>>(event_types);
    k_build<<<(NPOS*NC + 255)/256, 256>>>(event_times, event_types, emb);
    k_wc<<<(NL*TILE_ELEMS + 255)/256, 256>>>(k3W, k3b, skipW, skipb);
    {
        dim3 g((NPOS*KS + 255)/256, NL);
        k_mlp_all<<<g, 256>>>(k1W, k1b, k2W, k2b);
    }

    const int dil[NL] = {1, 2, 4, 8};
    for (int i = 0; i < NL; i++) {
        k_fused<<<NTILE, 256>>>(i, dil[i], i == 0);
        k_stats<<<1, 1024>>>(i, gamma, beta);
    }
    k_apply<<<(NPOS*NC + 255)/256, 256>>>(out, (NL-1) & 1);
}

// round 8
// speedup vs baseline: 2.0508x; 1.1501x over previous
#include <cuda_runtime.h>

#define BS 8
#define LQ 2049
#define NC 32
#define NH 16
#define KS 5
#define NL 4
#define NPOS (BS*LQ)            // 16392
#define TILE 16
#define NTILE 1025              // ceil(NPOS/16)
#define KA 584                  // 512 Gsum + 32 fsum + 32 enc + 1 one + 7 pad
#define KHALF (KA/2)            // 292
#define TILE_ELEMS (KA*NC)      // 18688
#define ASTRIDE 596             // padded A row stride

// -------- device scratch --------
__device__ __align__(16) float g_times[BS*LQ];
__device__ __align__(16) float g_enc[NPOS*NC];
__device__ __align__(16) float g_raw[2][NTILE*TILE*NC];   // ping-pong
__device__ __align__(16) float g_H2[NL*NPOS*KS*NH];       // 21 MB, all layers
__device__ __align__(16) float g_Wc[NL*TILE_ELEMS];
__device__ __align__(16) float g_psum[NTILE*NC];
__device__ __align__(16) float g_psq[NTILE*NC];
__device__ __align__(16) float g_bn[2*NC];
__device__ int g_maxtype;

__device__ __forceinline__ float lrelu(float x) { return x >= 0.f ? x : 0.1f*x; }

// -------- prep: global max of event_types --------
__global__ void k_max(const int* __restrict__ types) {
    __shared__ int sm[1024];
    int t = threadIdx.x, m = 0;
    for (int i = t; i < BS*2048; i += 1024) m = max(m, types[i]);
    sm[t] = m;
    for (int s = 512; s > 0; s >>= 1) {
        __syncthreads();
        if (t < s) sm[t] = max(sm[t], sm[t+s]);
    }
    __syncthreads();
    if (t == 0) g_maxtype = sm[0];
}

// -------- prep: build times + embedded enc --------
__global__ void k_build(const float* __restrict__ et, const int* __restrict__ ty,
                        const float* __restrict__ emb) {
    int idx = blockIdx.x*blockDim.x + threadIdx.x;
    if (idx >= NPOS*NC) return;
    int pos = idx >> 5, c = idx & 31;
    int b = pos / LQ, l = pos - b*LQ;
    float tv = (l == 0) ? 0.f : et[b*2048 + l - 1];
    if (c == 0) g_times[pos] = tv;
    int tp = (l == 0) ? (g_maxtype + 1) : ty[b*2048 + l - 1];
    g_enc[idx] = (tp == 0) ? 0.f : emb[tp*NC + c];
}

// -------- prep: combined weight matrix Wc[layer][584][32] --------
__global__ void k_wc(const float* __restrict__ k3W, const float* __restrict__ k3b,
                     const float* __restrict__ skipW, const float* __restrict__ skipb) {
    int idx = blockIdx.x*blockDim.x + threadIdx.x;
    if (idx >= NL*TILE_ELEMS) return;
    int layer = idx / TILE_ELEMS;
    int rem = idx - layer*TILE_ELEMS;
    int r = rem >> 5, d = rem & 31;
    float v;
    if (r < 512)      v = k3W[layer*16384 + r*32 + d];
    else if (r < 544) v = k3b[layer*1024 + (r-512)*32 + d];
    else if (r < 576) v = skipW[layer*1024 + (r-544)*32 + d];
    else if (r == 576) v = skipb[layer*32 + d];
    else v = 0.f;
    g_Wc[idx] = v;
}

// -------- ALL layers' kernel MLPs upfront: H2[layer][pos][k][16] --------
__global__ __launch_bounds__(256) void k_mlp_all(
        const float* __restrict__ k1W, const float* __restrict__ k1b,
        const float* __restrict__ k2W, const float* __restrict__ k2b) {
    int layer = blockIdx.y;
    int dil = 1 << layer;
    __shared__ float sk1[NH], sk1b[NH], sk2[NH*NH], sk2b[NH];
    int t = threadIdx.x;
    if (t < NH) { sk1[t] = k1W[layer*NH + t]; sk1b[t] = k1b[layer*NH + t];
                  sk2b[t] = k2b[layer*NH + t]; }
    sk2[t] = k2W[layer*NH*NH + t];
    __syncthreads();
    int idx = blockIdx.x*256 + t;
    if (idx >= NPOS*KS) return;
    int pos = idx / KS, k = idx - pos*KS;
    int b = pos / LQ, l = pos - b*LQ;
    float out[NH];
    bool valid = false;
    int j = l - k*dil;
    float tl = g_times[pos];
    if (j >= 0 && tl != 0.f) {
        float tj = g_times[b*LQ + j];
        if (tj != 0.f) {
            valid = true;
            float dt = tl - tj;
            float h1[NH];
            #pragma unroll
            for (int h = 0; h < NH; h++) h1[h] = lrelu(fmaf(dt, sk1[h], sk1b[h]));
            #pragma unroll
            for (int hh = 0; hh < NH; hh++) {
                float s = sk2b[hh];
                #pragma unroll
                for (int x = 0; x < NH; x++) s = fmaf(h1[x], sk2[x*NH + hh], s);
                out[hh] = lrelu(s);
            }
        }
    }
    if (!valid) {
        #pragma unroll
        for (int h = 0; h < NH; h++) out[h] = 0.f;
    }
    float* dst = g_H2 + (size_t)((layer*NPOS + pos)*KS + k)*NH;
    #pragma unroll
    for (int q = 0; q < 4; q++)
        *reinterpret_cast<float4*>(dst + 4*q) =
            make_float4(out[4*q], out[4*q+1], out[4*q+2], out[4*q+3]);
}

// -------- fused: gather/Gsum build (static smem A) + f32x2 GEMM + BN partials
__global__ __launch_bounds__(256) void k_fused(int layer, int dil, int first) {
    __shared__ float s_bn[64];
    __shared__ __align__(16) float s_A[TILE*ASTRIDE];     // 38144 B
    __shared__ __align__(16) float s_red[TILE*NC];        // K-split reduction
    __shared__ __align__(16) float s_ps[TILE*NC], s_ps2[TILE*NC];
    int t = threadIdx.x;
    int lane = t & 31, warp = t >> 5;
    int tile = blockIdx.x;
    const float* raw_in = g_raw[(layer + 1) & 1];
    float* raw_out = g_raw[layer & 1];

    if (!first && t < 64) s_bn[t] = g_bn[t];
    __syncthreads();

    // ---- phase A: 8 warps x 2 positions; lane = channel c ----
    #pragma unroll
    for (int wp = 0; wp < 2; wp++) {
        int p = warp*2 + wp;
        int pos = tile*TILE + p;
        float G[NH];
        #pragma unroll
        for (int h = 0; h < NH; h++) G[h] = 0.f;
        float fs = 0.f, en = 0.f, one = 0.f;
        if (pos < NPOS) {
            one = 1.f;
            int b = pos / LQ, l = pos - b*LQ;
            float tl = g_times[pos];
            if (first) en = g_enc[pos*NC + lane];
            else {
                float v = fmaf(raw_in[pos*NC + lane], s_bn[lane], s_bn[32 + lane]);
                en = v >= 0.f ? v : 0.1f*v;
            }
            if (tl != 0.f) {
                const float* h2p = g_H2 + (size_t)((layer*NPOS + pos)*KS)*NH;
                for (int k = 0; k < KS; k++) {
                    int j = l - k*dil;
                    if (j < 0) break;
                    float tj = g_times[b*LQ + j];
                    if (tj != 0.f) {
                        int pj = pos - k*dil;
                        float g;
                        if (first) g = g_enc[pj*NC + lane];
                        else {
                            float v = fmaf(raw_in[pj*NC + lane], s_bn[lane], s_bn[32 + lane]);
                            g = v >= 0.f ? v : 0.1f*v;
                        }
                        fs += g;
                        float4 h0 = *reinterpret_cast<const float4*>(h2p + k*NH + 0);
                        float4 h1 = *reinterpret_cast<const float4*>(h2p + k*NH + 4);
                        float4 h2 = *reinterpret_cast<const float4*>(h2p + k*NH + 8);
                        float4 h3 = *reinterpret_cast<const float4*>(h2p + k*NH + 12);
                        G[0] = fmaf(h0.x, g, G[0]);  G[1] = fmaf(h0.y, g, G[1]);
                        G[2] = fmaf(h0.z, g, G[2]);  G[3] = fmaf(h0.w, g, G[3]);
                        G[4] = fmaf(h1.x, g, G[4]);  G[5] = fmaf(h1.y, g, G[5]);
                        G[6] = fmaf(h1.z, g, G[6]);  G[7] = fmaf(h1.w, g, G[7]);
                        G[8] = fmaf(h2.x, g, G[8]);  G[9] = fmaf(h2.y, g, G[9]);
                        G[10] = fmaf(h2.z, g, G[10]); G[11] = fmaf(h2.w, g, G[11]);
                        G[12] = fmaf(h3.x, g, G[12]); G[13] = fmaf(h3.y, g, G[13]);
                        G[14] = fmaf(h3.z, g, G[14]); G[15] = fmaf(h3.w, g, G[15]);
                    }
                }
            }
        }
        float* row = s_A + p*ASTRIDE;
        #pragma unroll
        for (int h = 0; h < NH; h++) row[h*32 + lane] = G[h];
        row[512 + lane] = fs;
        row[544 + lane] = en;
        if (lane == 0) row[576] = one;
        if (lane < 7)  row[577 + lane] = 0.f;
    }
    __syncthreads();

    // ---- GEMM: 2-way K-split, packed f32x2 FMA ----
    // thread = (ks, ty, tx): ks = K-half, ty = pos (0..15), tx = d-group (4 d)
    int ks = t >> 7;           // 0..1
    int ty = (t >> 3) & 15;    // pos in tile
    int tx = t & 7;            // d0 = 4*tx
    const float* Ap = s_A + ty*ASTRIDE + ks*KHALF;
    const float* Wl = g_Wc + layer*TILE_ELEMS + ks*KHALF*NC + 4*tx;
    unsigned long long acc0 = 0ULL, acc1 = 0ULL;   // packed (d0,d0+1), (d0+2,d0+3)
    #pragma unroll 4
    for (int kk = 0; kk < KHALF/4; kk++) {         // 73 iterations
        float4 a = *reinterpret_cast<const float4*>(Ap + kk*4);
        #pragma unroll
        for (int r = 0; r < 4; r++) {
            ulonglong2 w = *reinterpret_cast<const ulonglong2*>(Wl + (4*kk + r)*NC);
            float av = (r == 0) ? a.x : (r == 1) ? a.y : (r == 2) ? a.z : a.w;
            unsigned long long ap2;
            asm("mov.b64 %0, {%1, %1};" : "=l"(ap2) : "f"(av));
            asm("fma.rn.f32x2 %0, %1, %2, %0;" : "+l"(acc0) : "l"(ap2), "l"(w.x));
            asm("fma.rn.f32x2 %0, %1, %2, %0;" : "+l"(acc1) : "l"(ap2), "l"(w.y));
        }
    }
    float r0, r1, r2, r3;
    asm("mov.b64 {%0, %1}, %2;" : "=f"(r0), "=f"(r1) : "l"(acc0));
    asm("mov.b64 {%0, %1}, %2;" : "=f"(r2), "=f"(r3) : "l"(acc1));

    if (ks == 1)
        *reinterpret_cast<float4*>(&s_red[ty*32 + 4*tx]) = make_float4(r0, r1, r2, r3);
    __syncthreads();
    if (ks == 0) {
        float4 o = *reinterpret_cast<const float4*>(&s_red[ty*32 + 4*tx]);
        r0 += o.x; r1 += o.y; r2 += o.z; r3 += o.w;
        *reinterpret_cast<float4*>(raw_out + (size_t)(tile*TILE + ty)*NC + 4*tx) =
            make_float4(r0, r1, r2, r3);
        *reinterpret_cast<float4*>(&s_ps [ty*32 + 4*tx]) = make_float4(r0, r1, r2, r3);
        *reinterpret_cast<float4*>(&s_ps2[ty*32 + 4*tx]) =
            make_float4(r0*r0, r1*r1, r2*r2, r3*r3);
    }
    __syncthreads();
    if (t < 32) {
        float s = 0.f, s2 = 0.f;
        #pragma unroll
        for (int r = 0; r < TILE; r++) { s += s_ps[r*32 + t]; s2 += s_ps2[r*32 + t]; }
        g_psum[tile*32 + t] = s;
        g_psq [tile*32 + t] = s2;
    }
}

// -------- BN stats: 1024 threads, 32-way parallel per channel --------
__global__ __launch_bounds__(1024) void k_stats(int layer, const float* __restrict__ gamma,
                        const float* __restrict__ beta) {
    __shared__ float ss[32][33], ss2[32][33];
    int t = threadIdx.x;      // 1024
    int r = t >> 5, n = t & 31;
    float s = 0.f, s2 = 0.f;
    #pragma unroll 4
    for (int b = r; b < NTILE; b += 32) {
        s += g_psum[b*32 + n];
        s2 += g_psq[b*32 + n];
    }
    ss[r][n] = s; ss2[r][n] = s2;
    __syncthreads();
    if (t < 32) {
        float fs = 0.f, fs2 = 0.f;
        #pragma unroll
        for (int i = 0; i < 32; i++) { fs += ss[i][t]; fs2 += ss2[i][t]; }
        float inv = 1.0f / (float)NPOS;
        float mu = fs * inv;
        float var = fs2 * inv - mu*mu;
        float scale = rsqrtf(var + 1e-5f) * gamma[layer*32 + t];
        g_bn[t]      = scale;
        g_bn[32 + t] = beta[layer*32 + t] - mu*scale;
    }
}

// -------- final apply: BN + leaky ReLU -> output --------
__global__ void k_apply(float* dst, int buf) {
    int idx = blockIdx.x*blockDim.x + threadIdx.x;
    if (idx >= NPOS*NC) return;
    int n = idx & 31;
    float v = fmaf(g_raw[buf][idx], g_bn[n], g_bn[32 + n]);
    dst[idx] = v >= 0.f ? v : 0.1f*v;
}

extern "C" void kernel_launch(void* const* d_in, const int* in_sizes, int n_in,
                              void* d_out, int out_size) {
    const float* event_times = (const float*)d_in[0];
    const int*   event_types = (const int*)  d_in[1];
    const float* emb   = (const float*)d_in[2];
    const float* k1W   = (const float*)d_in[3];
    const float* k1b   = (const float*)d_in[4];
    const float* k2W   = (const float*)d_in[5];
    const float* k2b   = (const float*)d_in[6];
    const float* k3W   = (const float*)d_in[7];
    const float* k3b   = (const float*)d_in[8];
    const float* skipW = (const float*)d_in[9];
    const float* skipb = (const float*)d_in[10];
    const float* gamma = (const float*)d_in[11];
    const float* beta  = (const float*)d_in[12];
    float* out = (float*)d_out;

    k_max<<<1, 1024>>>(event_types);
    k_build<<<(NPOS*NC + 255)/256, 256>>>(event_times, event_types, emb);
    k_wc<<<(NL*TILE_ELEMS + 255)/256, 256>>>(k3W, k3b, skipW, skipb);
    {
        dim3 g((NPOS*KS + 255)/256, NL);
        k_mlp_all<<<g, 256>>>(k1W, k1b, k2W, k2b);
    }

    const int dil[NL] = {1, 2, 4, 8};
    for (int i = 0; i < NL; i++) {
        k_fused<<<NTILE, 256>>>(i, dil[i], i == 0);
        k_stats<<<1, 1024>>>(i, gamma, beta);
    }
    k_apply<<<(NPOS*NC + 255)/256, 256>>>(out, (NL-1) & 1);
}